// round 1
// baseline (speedup 1.0000x reference)
#include <cuda_runtime.h>
#include <math.h>

// NT-Xent loss, B=4096, D=256, T=0.5.
// Plan: normalize -> fused GEMM+exp+rowsum (sim never materialized) -> finalize.
// Since rows are unit vectors, |s_ij| <= 1/T = 2, so exp() never overflows and
// logsumexp needs no max subtraction:
//   lse_i = log( sum_j exp(s_ij) - e^2 + exp(pos_i) ),  loss = mean(lse_i - pos_i)

#define D      256
#define MAXB   4096
#define MAXN   (2 * MAXB)
#define INV_T  2.0f
#define E2     7.3890560989306495f   // exp(1/T * 1)

__device__ float g_reps[MAXN * D];    // normalized [z1; z2], 8 MB
__device__ float g_pos[MAXN];
__device__ float g_rowsum[MAXN];

// ---------------------------------------------------------------------------
// Kernel 1: normalize rows, compute pos_i = dot(n1_i, n2_i)/T, zero rowsums.
// One warp per pair-row i.
// ---------------------------------------------------------------------------
__global__ void normalize_kernel(const float* __restrict__ z1,
                                 const float* __restrict__ z2, int B) {
    int warp = (blockIdx.x * blockDim.x + threadIdx.x) >> 5;
    int lane = threadIdx.x & 31;
    if (warp >= B) return;

    const float* a = z1 + (size_t)warp * D;
    const float* b = z2 + (size_t)warp * D;

    float av[D / 32], bv[D / 32];
    float n1 = 0.f, n2 = 0.f, dp = 0.f;
#pragma unroll
    for (int t = 0; t < D / 32; t++) {
        float x = a[lane + 32 * t];
        float y = b[lane + 32 * t];
        av[t] = x; bv[t] = y;
        n1 = fmaf(x, x, n1);
        n2 = fmaf(y, y, n2);
        dp = fmaf(x, y, dp);
    }
#pragma unroll
    for (int off = 16; off; off >>= 1) {
        n1 += __shfl_xor_sync(0xffffffffu, n1, off);
        n2 += __shfl_xor_sync(0xffffffffu, n2, off);
        dp += __shfl_xor_sync(0xffffffffu, dp, off);
    }

    float inv1 = 1.f / fmaxf(sqrtf(n1), 1e-12f);
    float inv2 = 1.f / fmaxf(sqrtf(n2), 1e-12f);

    float* r1 = g_reps + (size_t)warp * D;
    float* r2 = g_reps + (size_t)(warp + B) * D;
#pragma unroll
    for (int t = 0; t < D / 32; t++) {
        r1[lane + 32 * t] = av[t] * inv1;
        r2[lane + 32 * t] = bv[t] * inv2;
    }
    if (lane == 0) {
        float pos = dp * inv1 * inv2 * INV_T;
        g_pos[warp]     = pos;
        g_pos[warp + B] = pos;
        g_rowsum[warp]     = 0.f;
        g_rowsum[warp + B] = 0.f;
    }
}

// ---------------------------------------------------------------------------
// Kernel 2: fused GEMM + exp + row-sum.
// Block computes a 128x128 tile of sim = reps @ reps^T (never stored),
// applies exp(s/T') in registers, reduces to 128 row-partials, atomicAdds.
// 256 threads, 8x8 micro-tile per thread, classic SGEMM smem tiling.
// ---------------------------------------------------------------------------
#define BM 128
#define BN 128
#define BK 16
#define TM 8
#define TN 8

__global__ __launch_bounds__(256) void simsum_kernel() {
    __shared__ float As[BK][BM];
    __shared__ float Bs[BK][BN];

    int bi  = blockIdx.y;          // row tile
    int bj  = blockIdx.x;          // col tile
    int tid = threadIdx.x;
    int tx  = tid & 15;
    int ty  = tid >> 4;

    const float* Abase = g_reps + (size_t)bi * BM * D;
    const float* Bbase = g_reps + (size_t)bj * BN * D;

    float acc[TM][TN];
#pragma unroll
    for (int i = 0; i < TM; i++)
#pragma unroll
        for (int j = 0; j < TN; j++) acc[i][j] = 0.f;

    for (int k0 = 0; k0 < D; k0 += BK) {
        // Load 128x16 A and B tiles (512 float4 each; 2 per thread), transposed
        // into smem so the inner loop reads As[k][m] / Bs[k][n].
#pragma unroll
        for (int v = 0; v < 2; v++) {
            int e   = tid + v * 256;
            int row = e >> 2;
            int c4  = e & 3;
            float4 a = *(const float4*)(Abase + (size_t)row * D + k0 + c4 * 4);
            float4 b = *(const float4*)(Bbase + (size_t)row * D + k0 + c4 * 4);
            As[c4 * 4 + 0][row] = a.x; As[c4 * 4 + 1][row] = a.y;
            As[c4 * 4 + 2][row] = a.z; As[c4 * 4 + 3][row] = a.w;
            Bs[c4 * 4 + 0][row] = b.x; Bs[c4 * 4 + 1][row] = b.y;
            Bs[c4 * 4 + 2][row] = b.z; Bs[c4 * 4 + 3][row] = b.w;
        }
        __syncthreads();

#pragma unroll
        for (int k = 0; k < BK; k++) {
            float af[TM], bf[TN];
#pragma unroll
            for (int i = 0; i < TM; i++) af[i] = As[k][ty * TM + i];
#pragma unroll
            for (int j = 0; j < TN; j++) bf[j] = Bs[k][tx * TN + j];
#pragma unroll
            for (int i = 0; i < TM; i++)
#pragma unroll
                for (int j = 0; j < TN; j++)
                    acc[i][j] = fmaf(af[i], bf[j], acc[i][j]);
        }
        __syncthreads();
    }

    // Epilogue: exp + per-row partial sum, reduce across the 16 tx lanes,
    // one atomicAdd per row per block.
#pragma unroll
    for (int i = 0; i < TM; i++) {
        float rp = 0.f;
#pragma unroll
        for (int j = 0; j < TN; j++)
            rp += __expf(acc[i][j] * INV_T);
#pragma unroll
        for (int off = 8; off; off >>= 1)
            rp += __shfl_down_sync(0xffffffffu, rp, off, 16);
        if (tx == 0)
            atomicAdd(&g_rowsum[bi * BM + ty * TM + i], rp);
    }
}

// ---------------------------------------------------------------------------
// Kernel 3: finalize. lse_i = log(rowsum_i - e^2 + exp(pos_i)); mean(lse-pos).
// ---------------------------------------------------------------------------
__global__ void finalize_kernel(float* __restrict__ out, int N2) {
    __shared__ float sdata[256];
    int tid = threadIdx.x;
    float local = 0.f;
    for (int i = tid; i < N2; i += 256) {
        float pos = g_pos[i];
        float rs  = g_rowsum[i] + __expf(pos) - E2;
        local += logf(rs) - pos;
    }
    sdata[tid] = local;
    __syncthreads();
#pragma unroll
    for (int s = 128; s; s >>= 1) {
        if (tid < s) sdata[tid] += sdata[tid + s];
        __syncthreads();
    }
    if (tid == 0) out[0] = sdata[0] / (float)N2;
}

// ---------------------------------------------------------------------------
extern "C" void kernel_launch(void* const* d_in, const int* in_sizes, int n_in,
                              void* d_out, int out_size) {
    const float* z1 = (const float*)d_in[0];
    const float* z2 = (const float*)d_in[1];
    int B  = in_sizes[0] / D;   // 4096
    int N2 = 2 * B;             // 8192

    int threads = 256;
    int blocks  = (B * 32 + threads - 1) / threads;
    normalize_kernel<<<blocks, threads>>>(z1, z2, B);

    dim3 grid(N2 / BN, N2 / BM);   // 64 x 64
    simsum_kernel<<<grid, 256>>>();

    finalize_kernel<<<1, 256>>>((float*)d_out, N2);
}

// round 3
// speedup vs baseline: 6.3409x; 6.3409x over previous
#include <cuda_runtime.h>
#include <cuda_fp16.h>
#include <math.h>
#include <stdint.h>

// NT-Xent loss, B=4096, D=256, T=0.5 — mma.sync (HMMA) fp16 tensor-core version.
// lse_i = log( sum_j exp(2*s_ij) - e^2 + exp(2*pos_i) ), loss = mean(lse - pos)
// reps normalized to fp16 (entries in [-1,1]); pos computed exactly in fp32.

#define D      256
#define MAXB   4096
#define MAXN   (2 * MAXB)
#define INV_T  2.0f
#define E2     7.3890560989306495f

__device__ __half g_reps[MAXN * D];   // normalized [z1; z2] in fp16, 4 MB
__device__ float  g_pos[MAXN];
__device__ float  g_rowsum[MAXN];

// ---------------------------------------------------------------------------
// Kernel 1: normalize rows to fp16, compute pos (fp32), zero rowsums.
// ---------------------------------------------------------------------------
__global__ void normalize_kernel(const float* __restrict__ z1,
                                 const float* __restrict__ z2, int B) {
    int warp = (blockIdx.x * blockDim.x + threadIdx.x) >> 5;
    int lane = threadIdx.x & 31;
    if (warp >= B) return;

    const float* a = z1 + (size_t)warp * D;
    const float* b = z2 + (size_t)warp * D;

    float av[D / 32], bv[D / 32];
    float n1 = 0.f, n2 = 0.f, dp = 0.f;
#pragma unroll
    for (int t = 0; t < D / 32; t++) {
        float x = a[lane + 32 * t];
        float y = b[lane + 32 * t];
        av[t] = x; bv[t] = y;
        n1 = fmaf(x, x, n1);
        n2 = fmaf(y, y, n2);
        dp = fmaf(x, y, dp);
    }
#pragma unroll
    for (int off = 16; off; off >>= 1) {
        n1 += __shfl_xor_sync(0xffffffffu, n1, off);
        n2 += __shfl_xor_sync(0xffffffffu, n2, off);
        dp += __shfl_xor_sync(0xffffffffu, dp, off);
    }

    float inv1 = 1.f / fmaxf(sqrtf(n1), 1e-12f);
    float inv2 = 1.f / fmaxf(sqrtf(n2), 1e-12f);

    __half* r1 = g_reps + (size_t)warp * D;
    __half* r2 = g_reps + (size_t)(warp + B) * D;
#pragma unroll
    for (int t = 0; t < D / 32; t++) {
        r1[lane + 32 * t] = __float2half_rn(av[t] * inv1);
        r2[lane + 32 * t] = __float2half_rn(bv[t] * inv2);
    }
    if (lane == 0) {
        float pos = dp * inv1 * inv2 * INV_T;
        g_pos[warp]        = pos;
        g_pos[warp + B]    = pos;
        g_rowsum[warp]     = 0.f;
        g_rowsum[warp + B] = 0.f;
    }
}

// ---------------------------------------------------------------------------
// PTX helpers (baseline PTX, compiles at compute_100)
// ---------------------------------------------------------------------------
__device__ __forceinline__ uint32_t smem_u32(const void* p) {
    return (uint32_t)__cvta_generic_to_shared(p);
}

__device__ __forceinline__ void cpasync16(uint32_t dst, const void* src) {
    asm volatile("cp.async.cg.shared.global [%0], [%1], 16;"
                 :: "r"(dst), "l"(src) : "memory");
}
#define CP_COMMIT() asm volatile("cp.async.commit_group;" ::: "memory")
#define CP_WAIT(n)  asm volatile("cp.async.wait_group %0;" :: "n"(n) : "memory")

__device__ __forceinline__ void ldsm_x4(uint32_t* r, uint32_t addr) {
    asm volatile("ldmatrix.sync.aligned.m8n8.x4.shared.b16 {%0,%1,%2,%3}, [%4];"
                 : "=r"(r[0]), "=r"(r[1]), "=r"(r[2]), "=r"(r[3]) : "r"(addr));
}
__device__ __forceinline__ void ldsm_x2(uint32_t* r, uint32_t addr) {
    asm volatile("ldmatrix.sync.aligned.m8n8.x2.shared.b16 {%0,%1}, [%2];"
                 : "=r"(r[0]), "=r"(r[1]) : "r"(addr));
}

__device__ __forceinline__ void mma16816(float* c, const uint32_t* a,
                                         const uint32_t* b) {
    asm volatile(
        "mma.sync.aligned.m16n8k16.row.col.f32.f16.f16.f32 "
        "{%0,%1,%2,%3}, {%4,%5,%6,%7}, {%8,%9}, {%0,%1,%2,%3};"
        : "+f"(c[0]), "+f"(c[1]), "+f"(c[2]), "+f"(c[3])
        : "r"(a[0]), "r"(a[1]), "r"(a[2]), "r"(a[3]), "r"(b[0]), "r"(b[1]));
}

// ---------------------------------------------------------------------------
// Kernel 2: fused HMMA GEMM (128x128 block tile) + exp/row-sum epilogue.
// BK=32 halves per k-step, cp.async 2-stage pipeline.
// 8 warps as 2(m) x 4(n); warp tile 64x32; m16n8k16 grid 4x4 per warp per k16.
// Smem rows padded to 40 halves (80 B) -> conflict-free LDSM phases.
// ---------------------------------------------------------------------------
#define BM 128
#define BN 128
#define BK 32
#define NKT (D / BK)      // 8
#define RS  40            // padded row stride in halves (80 bytes)

__global__ __launch_bounds__(256, 2) void simsum_kernel() {
    __shared__ __align__(16) __half As[2][BM * RS];
    __shared__ __align__(16) __half Bs[2][BN * RS];

    int tid  = threadIdx.x;
    int wid  = tid >> 5;
    int lane = tid & 31;
    int bi   = blockIdx.y;
    int bj   = blockIdx.x;

    int wm = wid >> 2;           // 0..1
    int wn = wid & 3;            // 0..3
    int mbase = wm * 64;
    int nbase = wn * 32;

    const __half* Ag = g_reps + (size_t)bi * BM * D;
    const __half* Bg = g_reps + (size_t)bj * BN * D;

    // per-thread copy coordinates: 2 x 16B for A and B per stage
    int crow0 = tid >> 2;              // 0..63
    int cseg  = tid & 3;               // 0..3 (16B segment within 64B row)

    float acc[4][4][4];
#pragma unroll
    for (int i = 0; i < 4; i++)
#pragma unroll
        for (int j = 0; j < 4; j++)
#pragma unroll
            for (int k = 0; k < 4; k++) acc[i][j][k] = 0.f;

    uint32_t as_addr[2] = { smem_u32(As[0]), smem_u32(As[1]) };
    uint32_t bs_addr[2] = { smem_u32(Bs[0]), smem_u32(Bs[1]) };

    // ---- async copy of one k-chunk into stage s ----
    auto issue_copy = [&](int s, int kt) {
        int k0 = kt * BK;
#pragma unroll
        for (int i = 0; i < 2; i++) {
            int row = crow0 + 64 * i;
            uint32_t dsto = (uint32_t)(row * RS + cseg * 8) * 2u;
            cpasync16(as_addr[s] + dsto, Ag + (size_t)row * D + k0 + cseg * 8);
            cpasync16(bs_addr[s] + dsto, Bg + (size_t)row * D + k0 + cseg * 8);
        }
        CP_COMMIT();
    };

    issue_copy(0, 0);

    for (int kt = 0; kt < NKT; kt++) {
        if (kt + 1 < NKT) {
            issue_copy((kt + 1) & 1, kt + 1);
            CP_WAIT(1);
        } else {
            CP_WAIT(0);
        }
        __syncthreads();

        int s = kt & 1;
        uint32_t ab = as_addr[s];
        uint32_t bb = bs_addr[s];

#pragma unroll
        for (int kk = 0; kk < 2; kk++) {
            uint32_t a[4][4], b[4][2];
#pragma unroll
            for (int mi = 0; mi < 4; mi++) {
                int r = mbase + mi * 16 + (lane & 15);
                uint32_t addr = ab + (uint32_t)(r * RS + kk * 16 + ((lane >> 4) << 3)) * 2u;
                ldsm_x4(a[mi], addr);
            }
#pragma unroll
            for (int ni = 0; ni < 4; ni++) {
                int r = nbase + ni * 8 + (lane & 7);
                uint32_t addr = bb + (uint32_t)(r * RS + kk * 16 + (((lane >> 3) & 1) << 3)) * 2u;
                ldsm_x2(b[ni], addr);
            }
#pragma unroll
            for (int mi = 0; mi < 4; mi++)
#pragma unroll
                for (int ni = 0; ni < 4; ni++)
                    mma16816(acc[mi][ni], a[mi], b[ni]);
        }
        __syncthreads();
    }

    // ---- epilogue: exp + row-sum ----
    float* rowbuf = (float*)As;   // reuse smem (synced above)
    if (tid < BM) rowbuf[tid] = 0.f;
    __syncthreads();

    int g  = lane >> 2;
    int tc = lane & 3;
#pragma unroll
    for (int mi = 0; mi < 4; mi++) {
#pragma unroll
        for (int h = 0; h < 2; h++) {
            float s = 0.f;
#pragma unroll
            for (int ni = 0; ni < 4; ni++) {
                s += __expf(INV_T * acc[mi][ni][2 * h]);
                s += __expf(INV_T * acc[mi][ni][2 * h + 1]);
            }
            s += __shfl_xor_sync(0xffffffffu, s, 1);
            s += __shfl_xor_sync(0xffffffffu, s, 2);
            if (tc == 0)
                atomicAdd(&rowbuf[mbase + mi * 16 + h * 8 + g], s);
        }
    }
    __syncthreads();
    if (tid < BM)
        atomicAdd(&g_rowsum[bi * BM + tid], rowbuf[tid]);
}

// ---------------------------------------------------------------------------
// Kernel 3: finalize. lse_i = log(rowsum_i - e^2 + exp(pos_i)); mean(lse-pos).
// ---------------------------------------------------------------------------
__global__ void finalize_kernel(float* __restrict__ out, int N2) {
    __shared__ float sdata[256];
    int tid = threadIdx.x;
    float local = 0.f;
    for (int i = tid; i < N2; i += 256) {
        float pos = g_pos[i];
        float rs  = g_rowsum[i] + __expf(pos) - E2;
        local += logf(rs) - pos;
    }
    sdata[tid] = local;
    __syncthreads();
#pragma unroll
    for (int s = 128; s; s >>= 1) {
        if (tid < s) sdata[tid] += sdata[tid + s];
        __syncthreads();
    }
    if (tid == 0) out[0] = sdata[0] / (float)N2;
}

// ---------------------------------------------------------------------------
extern "C" void kernel_launch(void* const* d_in, const int* in_sizes, int n_in,
                              void* d_out, int out_size) {
    const float* z1 = (const float*)d_in[0];
    const float* z2 = (const float*)d_in[1];
    int B  = in_sizes[0] / D;   // 4096
    int N2 = 2 * B;             // 8192

    int threads = 256;
    int blocks  = (B * 32 + threads - 1) / threads;
    normalize_kernel<<<blocks, threads>>>(z1, z2, B);

    dim3 grid(N2 / BN, N2 / BM);   // 64 x 64
    simsum_kernel<<<grid, 256>>>();

    finalize_kernel<<<1, 256>>>((float*)d_out, N2);
}

// round 4
// speedup vs baseline: 9.4438x; 1.4893x over previous
#include <cuda_runtime.h>
#include <cuda_fp16.h>
#include <math.h>
#include <stdint.h>

// NT-Xent loss, B=4096, D=256, T=0.5 — HMMA fp16, symmetric-half GEMM.
// sim is symmetric: compute upper-triangle tiles only; off-diagonal tiles
// contribute row-sums (to bi rows) AND col-sums (to bj rows) of exp(sim).
// lse_i = log( sum_j exp(2*s_ij) - e^2 + exp(2*pos_i) ), loss = mean(lse - pos)

#define D      256
#define MAXB   4096
#define MAXN   (2 * MAXB)
#define INV_T  2.0f
#define E2     7.3890560989306495f
#define NT     64               // tile grid dimension (8192/128)

__device__ __half g_reps[MAXN * D];
__device__ float  g_pos[MAXN];
__device__ float  g_rowsum[MAXN];

// ---------------------------------------------------------------------------
// Kernel 1: normalize rows to fp16, compute pos (fp32), zero rowsums.
// ---------------------------------------------------------------------------
__global__ void normalize_kernel(const float* __restrict__ z1,
                                 const float* __restrict__ z2, int B) {
    int warp = (blockIdx.x * blockDim.x + threadIdx.x) >> 5;
    int lane = threadIdx.x & 31;
    if (warp >= B) return;

    const float* a = z1 + (size_t)warp * D;
    const float* b = z2 + (size_t)warp * D;

    float av[D / 32], bv[D / 32];
    float n1 = 0.f, n2 = 0.f, dp = 0.f;
#pragma unroll
    for (int t = 0; t < D / 32; t++) {
        float x = a[lane + 32 * t];
        float y = b[lane + 32 * t];
        av[t] = x; bv[t] = y;
        n1 = fmaf(x, x, n1);
        n2 = fmaf(y, y, n2);
        dp = fmaf(x, y, dp);
    }
#pragma unroll
    for (int off = 16; off; off >>= 1) {
        n1 += __shfl_xor_sync(0xffffffffu, n1, off);
        n2 += __shfl_xor_sync(0xffffffffu, n2, off);
        dp += __shfl_xor_sync(0xffffffffu, dp, off);
    }

    float inv1 = 1.f / fmaxf(sqrtf(n1), 1e-12f);
    float inv2 = 1.f / fmaxf(sqrtf(n2), 1e-12f);

    __half* r1 = g_reps + (size_t)warp * D;
    __half* r2 = g_reps + (size_t)(warp + B) * D;
#pragma unroll
    for (int t = 0; t < D / 32; t++) {
        r1[lane + 32 * t] = __float2half_rn(av[t] * inv1);
        r2[lane + 32 * t] = __float2half_rn(bv[t] * inv2);
    }
    if (lane == 0) {
        float pos = dp * inv1 * inv2 * INV_T;
        g_pos[warp]        = pos;
        g_pos[warp + B]    = pos;
        g_rowsum[warp]     = 0.f;
        g_rowsum[warp + B] = 0.f;
    }
}

// ---------------------------------------------------------------------------
// PTX helpers
// ---------------------------------------------------------------------------
__device__ __forceinline__ uint32_t smem_u32(const void* p) {
    return (uint32_t)__cvta_generic_to_shared(p);
}
__device__ __forceinline__ void cpasync16(uint32_t dst, const void* src) {
    asm volatile("cp.async.cg.shared.global [%0], [%1], 16;"
                 :: "r"(dst), "l"(src) : "memory");
}
#define CP_COMMIT() asm volatile("cp.async.commit_group;" ::: "memory")
#define CP_WAIT(n)  asm volatile("cp.async.wait_group %0;" :: "n"(n) : "memory")

__device__ __forceinline__ void ldsm_x4(uint32_t* r, uint32_t addr) {
    asm volatile("ldmatrix.sync.aligned.m8n8.x4.shared.b16 {%0,%1,%2,%3}, [%4];"
                 : "=r"(r[0]), "=r"(r[1]), "=r"(r[2]), "=r"(r[3]) : "r"(addr));
}
__device__ __forceinline__ void ldsm_x2(uint32_t* r, uint32_t addr) {
    asm volatile("ldmatrix.sync.aligned.m8n8.x2.shared.b16 {%0,%1}, [%2];"
                 : "=r"(r[0]), "=r"(r[1]) : "r"(addr));
}
__device__ __forceinline__ void mma16816(float* c, const uint32_t* a,
                                         const uint32_t* b) {
    asm volatile(
        "mma.sync.aligned.m16n8k16.row.col.f32.f16.f16.f32 "
        "{%0,%1,%2,%3}, {%4,%5,%6,%7}, {%8,%9}, {%0,%1,%2,%3};"
        : "+f"(c[0]), "+f"(c[1]), "+f"(c[2]), "+f"(c[3])
        : "r"(a[0]), "r"(a[1]), "r"(a[2]), "r"(a[3]), "r"(b[0]), "r"(b[1]));
}

// ---------------------------------------------------------------------------
// Kernel 2: symmetric-half fused HMMA GEMM + exp row/col-sum epilogue.
// 1D grid of 2080 upper-triangle tiles; decode linear index -> (bi, bj).
// ---------------------------------------------------------------------------
#define BM 128
#define BN 128
#define BK 32
#define NKT (D / BK)      // 8
#define RS  40            // padded row stride in halves (80 bytes)

__global__ __launch_bounds__(256, 2) void simsum_kernel() {
    __shared__ __align__(16) __half As[2][BM * RS];
    __shared__ __align__(16) __half Bs[2][BN * RS];

    int tid  = threadIdx.x;
    int wid  = tid >> 5;
    int lane = tid & 31;

    // decode upper-triangle tile index: row bi starts at S(bi)=bi*NT - bi(bi-1)/2
    int t  = blockIdx.x;
    int bi = (int)((2.0f * NT + 1.0f
                    - sqrtf((2.0f * NT + 1.0f) * (2.0f * NT + 1.0f) - 8.0f * (float)t))
                   * 0.5f);
    if (bi > NT - 1) bi = NT - 1;
    while (bi * NT - bi * (bi - 1) / 2 > t) bi--;
    while ((bi + 1) * NT - (bi + 1) * bi / 2 <= t) bi++;
    int bj = bi + (t - (bi * NT - bi * (bi - 1) / 2));

    int wm = wid >> 2;           // 0..1
    int wn = wid & 3;            // 0..3
    int mbase = wm * 64;
    int nbase = wn * 32;

    const __half* Ag = g_reps + (size_t)bi * BM * D;
    const __half* Bg = g_reps + (size_t)bj * BN * D;

    int crow0 = tid >> 2;
    int cseg  = tid & 3;

    float acc[4][4][4];
#pragma unroll
    for (int i = 0; i < 4; i++)
#pragma unroll
        for (int j = 0; j < 4; j++)
#pragma unroll
            for (int k = 0; k < 4; k++) acc[i][j][k] = 0.f;

    uint32_t as_addr[2] = { smem_u32(As[0]), smem_u32(As[1]) };
    uint32_t bs_addr[2] = { smem_u32(Bs[0]), smem_u32(Bs[1]) };

    auto issue_copy = [&](int s, int kt) {
        int k0 = kt * BK;
#pragma unroll
        for (int i = 0; i < 2; i++) {
            int row = crow0 + 64 * i;
            uint32_t dsto = (uint32_t)(row * RS + cseg * 8) * 2u;
            cpasync16(as_addr[s] + dsto, Ag + (size_t)row * D + k0 + cseg * 8);
            cpasync16(bs_addr[s] + dsto, Bg + (size_t)row * D + k0 + cseg * 8);
        }
        CP_COMMIT();
    };

    issue_copy(0, 0);

    for (int kt = 0; kt < NKT; kt++) {
        if (kt + 1 < NKT) {
            issue_copy((kt + 1) & 1, kt + 1);
            CP_WAIT(1);
        } else {
            CP_WAIT(0);
        }
        __syncthreads();

        int s = kt & 1;
        uint32_t ab = as_addr[s];
        uint32_t bb = bs_addr[s];

#pragma unroll
        for (int kk = 0; kk < 2; kk++) {
            uint32_t a[4][4], b[4][2];
#pragma unroll
            for (int mi = 0; mi < 4; mi++) {
                int r = mbase + mi * 16 + (lane & 15);
                uint32_t addr = ab + (uint32_t)(r * RS + kk * 16 + ((lane >> 4) << 3)) * 2u;
                ldsm_x4(a[mi], addr);
            }
#pragma unroll
            for (int ni = 0; ni < 4; ni++) {
                int r = nbase + ni * 8 + (lane & 7);
                uint32_t addr = bb + (uint32_t)(r * RS + kk * 16 + (((lane >> 3) & 1) << 3)) * 2u;
                ldsm_x2(b[ni], addr);
            }
#pragma unroll
            for (int mi = 0; mi < 4; mi++)
#pragma unroll
                for (int ni = 0; ni < 4; ni++)
                    mma16816(acc[mi][ni], a[mi], b[ni]);
        }
        __syncthreads();
    }

    // ---- epilogue: exp once; accumulate row-sums AND col-sums ----
    float* rowbuf = (float*)As[0];          // 128 floats
    float* colbuf = (float*)Bs[0];          // 128 floats
    if (tid < BM) { rowbuf[tid] = 0.f; colbuf[tid] = 0.f; }
    __syncthreads();

    int g  = lane >> 2;       // accumulator row-group (0..7)
    int tc = lane & 3;        // accumulator col-pair (0..3)

    float cs[4][2];
#pragma unroll
    for (int ni = 0; ni < 4; ni++) { cs[ni][0] = 0.f; cs[ni][1] = 0.f; }

#pragma unroll
    for (int mi = 0; mi < 4; mi++) {
#pragma unroll
        for (int h = 0; h < 2; h++) {
            float s = 0.f;
#pragma unroll
            for (int ni = 0; ni < 4; ni++) {
#pragma unroll
                for (int e = 0; e < 2; e++) {
                    float ex = __expf(INV_T * acc[mi][ni][2 * h + e]);
                    s += ex;
                    cs[ni][e] += ex;
                }
            }
            s += __shfl_xor_sync(0xffffffffu, s, 1);
            s += __shfl_xor_sync(0xffffffffu, s, 2);
            if (tc == 0)
                atomicAdd(&rowbuf[mbase + mi * 16 + h * 8 + g], s);
        }
    }
#pragma unroll
    for (int ni = 0; ni < 4; ni++) {
#pragma unroll
        for (int e = 0; e < 2; e++) {
            float c = cs[ni][e];
            c += __shfl_xor_sync(0xffffffffu, c, 4);
            c += __shfl_xor_sync(0xffffffffu, c, 8);
            c += __shfl_xor_sync(0xffffffffu, c, 16);
            if (g == 0)
                atomicAdd(&colbuf[nbase + ni * 8 + 2 * tc + e], c);
        }
    }
    __syncthreads();

    if (tid < BM) {
        atomicAdd(&g_rowsum[bi * BM + tid], rowbuf[tid]);
        if (bi != bj)
            atomicAdd(&g_rowsum[bj * BN + tid], colbuf[tid]);
    }
}

// ---------------------------------------------------------------------------
// Kernel 3: finalize.
// ---------------------------------------------------------------------------
__global__ void finalize_kernel(float* __restrict__ out, int N2) {
    __shared__ float sdata[256];
    int tid = threadIdx.x;
    float local = 0.f;
    for (int i = tid; i < N2; i += 256) {
        float pos = g_pos[i];
        float rs  = g_rowsum[i] + __expf(pos) - E2;
        local += logf(rs) - pos;
    }
    sdata[tid] = local;
    __syncthreads();
#pragma unroll
    for (int s = 128; s; s >>= 1) {
        if (tid < s) sdata[tid] += sdata[tid + s];
        __syncthreads();
    }
    if (tid == 0) out[0] = sdata[0] / (float)N2;
}

// ---------------------------------------------------------------------------
extern "C" void kernel_launch(void* const* d_in, const int* in_sizes, int n_in,
                              void* d_out, int out_size) {
    const float* z1 = (const float*)d_in[0];
    const float* z2 = (const float*)d_in[1];
    int B  = in_sizes[0] / D;   // 4096
    int N2 = 2 * B;             // 8192

    int threads = 256;
    int blocks  = (B * 32 + threads - 1) / threads;
    normalize_kernel<<<blocks, threads>>>(z1, z2, B);

    int ntiles = NT * (NT + 1) / 2;   // 2080
    simsum_kernel<<<ntiles, 256>>>();

    finalize_kernel<<<1, 256>>>((float*)d_out, N2);
}